// round 1
// baseline (speedup 1.0000x reference)
#include <cuda_runtime.h>
#include <cuda_bf16.h>
#include <cstdint>

// Problem-fixed maxima (from reference setup_inputs): N=20000, E=320000, D up to 512
#define MAXN 20000
#define MAXE 320000
#define MAXF 512

// -------- scratch (static device memory; no allocations allowed) --------
__device__ int   g_indeg[MAXN];
__device__ float g_dis[MAXN];
__device__ int   g_offsets[MAXN + 1];
__device__ int   g_cursor[MAXN];
__device__ int   g_csr_src[MAXE];
__device__ float g_csr_norm[MAXE];
__device__ float g_h0[(size_t)MAXN * MAXF];
__device__ float g_h1[(size_t)MAXN * MAXF];

// ---------------- preprocessing ----------------
__global__ void zero_indeg_kernel(int n) {
    int i = blockIdx.x * blockDim.x + threadIdx.x;
    if (i < n) g_indeg[i] = 0;
}

__global__ void count_indeg_kernel(const int* __restrict__ dst, int e) {
    int i = blockIdx.x * blockDim.x + threadIdx.x;
    if (i < e) atomicAdd(&g_indeg[dst[i]], 1);
}

__global__ void compute_dis_kernel(int n) {
    int i = blockIdx.x * blockDim.x + threadIdx.x;
    if (i < n) g_dis[i] = rsqrtf((float)(g_indeg[i] + 1));  // +1 self loop
}

// exclusive prefix sum of g_indeg into g_offsets; single block of 1024
__global__ void scan_kernel(int n) {
    __shared__ int sh[1024];
    int carry = 0;
    for (int base = 0; base < n; base += 1024) {
        int i = base + (int)threadIdx.x;
        int v = (i < n) ? g_indeg[i] : 0;
        sh[threadIdx.x] = v;
        __syncthreads();
        #pragma unroll
        for (int off = 1; off < 1024; off <<= 1) {
            int t = (threadIdx.x >= (unsigned)off) ? sh[threadIdx.x - off] : 0;
            __syncthreads();
            sh[threadIdx.x] += t;
            __syncthreads();
        }
        int inc = sh[threadIdx.x];
        if (i < n) {
            g_offsets[i] = carry + inc - v;   // exclusive
            g_cursor[i]  = carry + inc - v;
        }
        carry += sh[1023];
        __syncthreads();
    }
    if (threadIdx.x == 0) g_offsets[n] = carry;
}

__global__ void fill_csr_kernel(const int* __restrict__ src,
                                const int* __restrict__ dst, int e) {
    int i = blockIdx.x * blockDim.x + threadIdx.x;
    if (i < e) {
        int s = src[i], d = dst[i];
        int pos = atomicAdd(&g_cursor[d], 1);
        g_csr_src[pos]  = s;
        g_csr_norm[pos] = g_dis[s] * g_dis[d];
    }
}

// ---------------- SGEMM: C[M,N] = A[M,K] @ B[K,N]  (row-major) ----------------
// 128x128 block tile, BK=8, 256 threads, 8x8 microtile. Requires N%128==0, K%8==0.
__global__ __launch_bounds__(256, 2)
void sgemm128_kernel(const float* __restrict__ A, const float* __restrict__ B,
                     float* __restrict__ C, int M, int N, int K) {
    __shared__ float As[8][128];
    __shared__ float Bs[8][128];

    const int tid = threadIdx.x;
    const int tx = tid % 16;          // col group
    const int ty = tid / 16;          // row group
    const int bx = blockIdx.x;        // col tile
    const int by = blockIdx.y;        // row tile

    float acc[8][8];
    #pragma unroll
    for (int m = 0; m < 8; m++)
        #pragma unroll
        for (int n2 = 0; n2 < 8; n2++) acc[m][n2] = 0.f;

    const int a_row = tid >> 1;           // 0..127
    const int a_col = (tid & 1) * 4;      // 0 or 4
    const int b_row = tid >> 5;           // 0..7
    const int b_col = (tid & 31) * 4;     // 0..124
    const int gRowA = by * 128 + a_row;

    for (int k0 = 0; k0 < K; k0 += 8) {
        float4 av = make_float4(0.f, 0.f, 0.f, 0.f);
        if (gRowA < M)
            av = *(const float4*)(A + (size_t)gRowA * K + k0 + a_col);
        As[a_col + 0][a_row] = av.x;
        As[a_col + 1][a_row] = av.y;
        As[a_col + 2][a_row] = av.z;
        As[a_col + 3][a_row] = av.w;

        float4 bv = *(const float4*)(B + (size_t)(k0 + b_row) * N + bx * 128 + b_col);
        *(float4*)(&Bs[b_row][b_col]) = bv;
        __syncthreads();

        #pragma unroll
        for (int k = 0; k < 8; k++) {
            float ar[8], br[8];
            #pragma unroll
            for (int m = 0; m < 8; m++) ar[m] = As[k][ty * 8 + m];
            #pragma unroll
            for (int n2 = 0; n2 < 8; n2++) br[n2] = Bs[k][tx * 8 + n2];
            #pragma unroll
            for (int m = 0; m < 8; m++)
                #pragma unroll
                for (int n2 = 0; n2 < 8; n2++)
                    acc[m][n2] += ar[m] * br[n2];
        }
        __syncthreads();
    }

    #pragma unroll
    for (int m = 0; m < 8; m++) {
        int gr = by * 128 + ty * 8 + m;
        if (gr < M) {
            float4* crow = (float4*)(C + (size_t)gr * N + bx * 128 + tx * 8);
            crow[0] = make_float4(acc[m][0], acc[m][1], acc[m][2], acc[m][3]);
            crow[1] = make_float4(acc[m][4], acc[m][5], acc[m][6], acc[m][7]);
        }
    }
}

// ---------------- aggregation: out = lrelu(segsum + self + bias) ----------------
template <int F>
__global__ void agg_kernel(const float* __restrict__ h, float* __restrict__ out,
                           const float* __restrict__ bias, int n) {
    const int i = blockIdx.x;
    constexpr int VPT = F / 128;
    const int t = threadIdx.x;

    float acc[VPT];
    const float di = g_dis[i];
    const float selfw = di * di;
    const float* hrow = h + (size_t)i * F;
    #pragma unroll
    for (int k = 0; k < VPT; k++) acc[k] = selfw * hrow[t + 128 * k];

    const int beg = g_offsets[i];
    const int end = g_offsets[i + 1];
    for (int j = beg; j < end; j++) {
        const int   s = g_csr_src[j];
        const float w = g_csr_norm[j];
        const float* hs = h + (size_t)s * F;
        #pragma unroll
        for (int k = 0; k < VPT; k++) acc[k] += w * hs[t + 128 * k];
    }
    #pragma unroll
    for (int k = 0; k < VPT; k++) {
        float v = acc[k] + bias[t + 128 * k];
        out[(size_t)i * F + t + 128 * k] = (v > 0.f) ? v : 0.15f * v;
    }
}

// ---------------- fused head: h(128) -> 16 -> lrelu(32) -> 2 ----------------
__global__ __launch_bounds__(256)
void head_kernel(const float* __restrict__ h,
                 const float* __restrict__ Wp,  const float* __restrict__ bp,
                 const float* __restrict__ Wf1, const float* __restrict__ bf1,
                 const float* __restrict__ Wf2, const float* __restrict__ bf2,
                 float* __restrict__ out, int n) {
    __shared__ float sWp[128 * 16];
    __shared__ float sWf1[16 * 32];
    __shared__ float sWf2[32 * 2];
    __shared__ float sbp[16], sbf1[32], sbf2[2];

    for (int i = threadIdx.x; i < 128 * 16; i += 256) sWp[i] = Wp[i];
    for (int i = threadIdx.x; i < 16 * 32;  i += 256) sWf1[i] = Wf1[i];
    if (threadIdx.x < 64) sWf2[threadIdx.x] = Wf2[threadIdx.x];
    if (threadIdx.x < 16) sbp[threadIdx.x]  = bp[threadIdx.x];
    if (threadIdx.x < 32) sbf1[threadIdx.x] = bf1[threadIdx.x];
    if (threadIdx.x < 2)  sbf2[threadIdx.x] = bf2[threadIdx.x];
    __syncthreads();

    const int warp = threadIdx.x / 32, lane = threadIdx.x % 32;
    const int node = blockIdx.x * 8 + warp;
    if (node >= n) return;

    float hv[4];
    const float* hr = h + (size_t)node * 128;
    #pragma unroll
    for (int k = 0; k < 4; k++) hv[k] = hr[lane + 32 * k];

    float s16[16];
    #pragma unroll
    for (int j = 0; j < 16; j++) {
        float p = 0.f;
        #pragma unroll
        for (int k = 0; k < 4; k++) p += hv[k] * sWp[(lane + 32 * k) * 16 + j];
        #pragma unroll
        for (int o = 16; o > 0; o >>= 1) p += __shfl_xor_sync(0xffffffffu, p, o);
        s16[j] = p + sbp[j];          // pre_fc: no activation
    }

    float tv = sbf1[lane];
    #pragma unroll
    for (int k = 0; k < 16; k++) tv += s16[k] * sWf1[k * 32 + lane];
    tv = (tv > 0.f) ? tv : 0.15f * tv;  // lrelu

    float v0 = tv * sWf2[lane * 2 + 0];
    float v1 = tv * sWf2[lane * 2 + 1];
    #pragma unroll
    for (int o = 16; o > 0; o >>= 1) {
        v0 += __shfl_xor_sync(0xffffffffu, v0, o);
        v1 += __shfl_xor_sync(0xffffffffu, v1, o);
    }
    if (lane == 0) {
        out[(size_t)node * 2 + 0] = v0 + sbf2[0];
        out[(size_t)node * 2 + 1] = v1 + sbf2[1];
    }
}

// ---------------- launch ----------------
extern "C" void kernel_launch(void* const* d_in, const int* in_sizes, int n_in,
                              void* d_out, int out_size) {
    const float* x   = (const float*)d_in[0];
    const int*   ei  = (const int*)  d_in[1];
    // d_in[2] = edge_attr (unused by reference path)
    const float* W1  = (const float*)d_in[3];
    const float* b1  = (const float*)d_in[4];
    const float* W2  = (const float*)d_in[5];
    const float* b2  = (const float*)d_in[6];
    const float* W3  = (const float*)d_in[7];
    const float* b3  = (const float*)d_in[8];
    const float* Wp  = (const float*)d_in[9];
    const float* bp  = (const float*)d_in[10];
    const float* Wf1 = (const float*)d_in[11];
    const float* bf1 = (const float*)d_in[12];
    const float* Wf2 = (const float*)d_in[13];
    const float* bf2 = (const float*)d_in[14];
    float* out = (float*)d_out;

    const int N = in_sizes[0] / 128;
    const int E = in_sizes[1] / 2;
    const int* src = ei;
    const int* dst = ei + E;

    float *h0, *h1;
    cudaGetSymbolAddress((void**)&h0, g_h0);
    cudaGetSymbolAddress((void**)&h1, g_h1);

    // --- preprocessing: degree, normalization, CSR-by-dst ---
    zero_indeg_kernel<<<(N + 255) / 256, 256>>>(N);
    count_indeg_kernel<<<(E + 255) / 256, 256>>>(dst, E);
    compute_dis_kernel<<<(N + 255) / 256, 256>>>(N);
    scan_kernel<<<1, 1024>>>(N);
    fill_csr_kernel<<<(E + 255) / 256, 256>>>(src, dst, E);

    // --- layer 1: 128 -> 512 ---
    {
        dim3 grid(512 / 128, (N + 127) / 128);
        sgemm128_kernel<<<grid, 256>>>(x, W1, h0, N, 512, 128);
        agg_kernel<512><<<N, 128>>>(h0, h1, b1, N);
    }
    // --- layer 2: 512 -> 256 ---
    {
        dim3 grid(256 / 128, (N + 127) / 128);
        sgemm128_kernel<<<grid, 256>>>(h1, W2, h0, N, 256, 512);
        agg_kernel<256><<<N, 128>>>(h0, h1, b2, N);
    }
    // --- layer 3: 256 -> 128 ---
    {
        dim3 grid(128 / 128, (N + 127) / 128);
        sgemm128_kernel<<<grid, 256>>>(h1, W3, h0, N, 128, 256);
        agg_kernel<128><<<N, 128>>>(h0, h1, b3, N);
    }
    // --- fused head ---
    head_kernel<<<(N + 7) / 8, 256>>>(h1, Wp, bp, Wf1, bf1, Wf2, bf2, out, N);
}

// round 3
// speedup vs baseline: 1.6876x; 1.6876x over previous
#include <cuda_runtime.h>
#include <cuda_fp16.h>
#include <cuda_bf16.h>
#include <cstdint>

// Problem-fixed maxima: N=20000, E=320000, F up to 512
#define MAXN 20000
#define MAXE 320000
#define MAXF 512

// -------- scratch (static device memory; no allocations allowed) --------
__device__ int    g_indeg[MAXN];
__device__ float  g_dis[MAXN];
__device__ int    g_offsets[MAXN + 1];
__device__ int    g_cursor[MAXN];
__device__ int    g_csr_src[MAXE];
__device__ float  g_csr_norm[MAXE];
__device__ float  g_h0[(size_t)MAXN * MAXF];
__device__ float  g_h1[(size_t)MAXN * MAXF];
__device__ __half g_Ahi[(size_t)MAXN * MAXF];
__device__ __half g_Alo[(size_t)MAXN * MAXF];
__device__ __half g_Bhi[(size_t)MAXF * MAXF];
__device__ __half g_Blo[(size_t)MAXF * MAXF];

__device__ __forceinline__ uint32_t smem_u32(const void* p) {
    uint32_t a;
    asm("{ .reg .u64 t; cvta.to.shared.u64 t, %1; cvt.u32.u64 %0, t; }" : "=r"(a) : "l"(p));
    return a;
}
__device__ __forceinline__ void ldsm_x4(uint32_t& r0, uint32_t& r1, uint32_t& r2, uint32_t& r3,
                                        uint32_t addr) {
    asm volatile("ldmatrix.sync.aligned.m8n8.x4.shared.b16 {%0,%1,%2,%3}, [%4];"
                 : "=r"(r0), "=r"(r1), "=r"(r2), "=r"(r3) : "r"(addr));
}
__device__ __forceinline__ void ldsm_x2(uint32_t& r0, uint32_t& r1, uint32_t addr) {
    asm volatile("ldmatrix.sync.aligned.m8n8.x2.shared.b16 {%0,%1}, [%2];"
                 : "=r"(r0), "=r"(r1) : "r"(addr));
}
__device__ __forceinline__ void mma16816(float* c, uint32_t a0, uint32_t a1, uint32_t a2,
                                         uint32_t a3, uint32_t b0, uint32_t b1) {
    asm volatile(
        "mma.sync.aligned.m16n8k16.row.col.f32.f16.f16.f32 "
        "{%0,%1,%2,%3}, {%4,%5,%6,%7}, {%8,%9}, {%0,%1,%2,%3};"
        : "+f"(c[0]), "+f"(c[1]), "+f"(c[2]), "+f"(c[3])
        : "r"(a0), "r"(a1), "r"(a2), "r"(a3), "r"(b0), "r"(b1));
}

// ---------------- preprocessing ----------------
__global__ void zero_indeg_kernel(int n) {
    int i = blockIdx.x * blockDim.x + threadIdx.x;
    if (i < n) g_indeg[i] = 0;
}
__global__ void count_indeg_kernel(const int* __restrict__ dst, int e) {
    int i = blockIdx.x * blockDim.x + threadIdx.x;
    if (i < e) atomicAdd(&g_indeg[dst[i]], 1);
}
__global__ void compute_dis_kernel(int n) {
    int i = blockIdx.x * blockDim.x + threadIdx.x;
    if (i < n) g_dis[i] = rsqrtf((float)(g_indeg[i] + 1));  // +1 self-loop
}

// hierarchical scan: 1 block, 1024 threads, each owns CH contiguous nodes
__global__ void scan_fast_kernel(int n) {
    const int tid = threadIdx.x;
    const int CH = (n + 1023) >> 10;   // <= 32
    const int base = tid * CH;
    int loc[32];
    int s = 0;
    for (int j = 0; j < CH; j++) {
        int i = base + j;
        int v = (i < n) ? g_indeg[i] : 0;
        loc[j] = s; s += v;
    }
    const int lane = tid & 31, w = tid >> 5;
    int inc = s;
    #pragma unroll
    for (int o = 1; o < 32; o <<= 1) { int t = __shfl_up_sync(~0u, inc, o); if (lane >= o) inc += t; }
    __shared__ int wsum[32];
    if (lane == 31) wsum[w] = inc;
    __syncthreads();
    if (w == 0) {
        int v = wsum[lane];
        int p = v;
        #pragma unroll
        for (int o = 1; o < 32; o <<= 1) { int t = __shfl_up_sync(~0u, p, o); if (lane >= o) p += t; }
        wsum[lane] = p - v;   // exclusive warp offsets
    }
    __syncthreads();
    const int off = wsum[w] + (inc - s);
    for (int j = 0; j < CH; j++) {
        int i = base + j;
        if (i < n) { int o2 = off + loc[j]; g_offsets[i] = o2; g_cursor[i] = o2; }
    }
    if (tid == 1023) g_offsets[n] = off + s;
}

__global__ void fill_csr_kernel(const int* __restrict__ src, const int* __restrict__ dst, int e) {
    int i = blockIdx.x * blockDim.x + threadIdx.x;
    if (i < e) {
        int s = src[i], d = dst[i];
        int pos = atomicAdd(&g_cursor[d], 1);
        g_csr_src[pos]  = s;
        g_csr_norm[pos] = g_dis[s] * g_dis[d];
    }
}

// -------- fp32 -> fp16 hi/lo split (elementwise, float4 vectorized) --------
__global__ void split_fp32_kernel(const float* __restrict__ in, __half* __restrict__ hi,
                                  __half* __restrict__ lo, int n4) {
    int i = blockIdx.x * blockDim.x + threadIdx.x;
    if (i < n4) {
        float4 v = ((const float4*)in)[i];
        __half h0 = __float2half_rn(v.x), h1 = __float2half_rn(v.y);
        __half h2 = __float2half_rn(v.z), h3 = __float2half_rn(v.w);
        float r0 = v.x - __half2float(h0), r1 = v.y - __half2float(h1);
        float r2 = v.z - __half2float(h2), r3 = v.w - __half2float(h3);
        ((__half2*)hi)[2 * i]     = __halves2half2(h0, h1);
        ((__half2*)hi)[2 * i + 1] = __halves2half2(h2, h3);
        ((__half2*)lo)[2 * i]     = __halves2half2(__float2half_rn(r0), __float2half_rn(r1));
        ((__half2*)lo)[2 * i + 1] = __halves2half2(__float2half_rn(r2), __float2half_rn(r3));
    }
}

// -------- W [K,N] row-major -> Bt [N,K] fp16 hi/lo split --------
__global__ void wsplit_kernel(const float* __restrict__ W, __half* __restrict__ hi,
                              __half* __restrict__ lo, int K, int N) {
    int i = blockIdx.x * blockDim.x + threadIdx.x;
    if (i < K * N) {
        int nn = i / K, kk = i % K;
        float f = W[(size_t)kk * N + nn];
        __half h = __float2half_rn(f);
        hi[i] = h;
        lo[i] = __float2half_rn(f - __half2float(h));
    }
}

// ============ HMMA fp16-split GEMM: C[M,N] = A[M,K] @ Bt[N,K]^T ============
// 128x128 block tile, BK=32, 256 threads (8 warps, 2m x 4n grid, 64x32 warp tile)
#define BM 128
#define BN 128
#define BK 32
#define APAD 8
#define ASTR (BK + APAD)   // 40 halves per row, conflict-free ldmatrix

__global__ void __launch_bounds__(256)
gemm_hmma_kernel(const __half* __restrict__ Ahi, const __half* __restrict__ Alo,
                 const __half* __restrict__ Bhi, const __half* __restrict__ Blo,
                 float* __restrict__ C, const float* __restrict__ bias,
                 int M, int N, int K, int bias_act) {
    __shared__ __half sAh[BM][ASTR];
    __shared__ __half sAl[BM][ASTR];
    __shared__ __half sBh[BN][ASTR];
    __shared__ __half sBl[BN][ASTR];

    const int tid = threadIdx.x;
    const int lane = tid & 31, wid = tid >> 5;
    const int wm = wid & 1;        // 0..1 (m)
    const int wn = wid >> 1;       // 0..3 (n)
    const int by = blockIdx.y;
    const int n0 = blockIdx.x * BN;

    float acc[4][4][4];
    #pragma unroll
    for (int mt = 0; mt < 4; mt++)
        #pragma unroll
        for (int nt = 0; nt < 4; nt++)
            #pragma unroll
            for (int r = 0; r < 4; r++) acc[mt][nt][r] = 0.f;

    // ldmatrix per-lane smem byte offsets
    const uint32_t aAh = smem_u32(&sAh[0][0]);
    const uint32_t aAl = smem_u32(&sAl[0][0]);
    const uint32_t aBh = smem_u32(&sBh[0][0]);
    const uint32_t aBl = smem_u32(&sBl[0][0]);
    const int a_msel = lane >> 3;              // 0..3
    const int a_rowin = (lane & 7) + ((a_msel & 1) << 3);
    const int a_colin = (a_msel >> 1) << 3;
    const int b_rowin = lane & 7;
    const int b_colin = ((lane >> 3) & 1) << 3;

    const int ldrow = tid >> 2;        // 0..63
    const int ldseg = (tid & 3) << 3;  // 0,8,16,24 halves

    for (int k0 = 0; k0 < K; k0 += BK) {
        // ---- load 4 tiles: 128 rows x 32 halves each; 2 rows per thread ----
        #pragma unroll
        for (int h = 0; h < 2; h++) {
            const int row = ldrow + h * 64;
            const int ar = by * BM + row;
            uint4 vh = make_uint4(0, 0, 0, 0), vl = make_uint4(0, 0, 0, 0);
            if (ar < M) {
                size_t ai = (size_t)ar * K + k0 + ldseg;
                vh = *(const uint4*)(Ahi + ai);
                vl = *(const uint4*)(Alo + ai);
            }
            *(uint4*)(&sAh[row][ldseg]) = vh;
            *(uint4*)(&sAl[row][ldseg]) = vl;
            size_t bi = (size_t)(n0 + row) * K + k0 + ldseg;
            *(uint4*)(&sBh[row][ldseg]) = *(const uint4*)(Bhi + bi);
            *(uint4*)(&sBl[row][ldseg]) = *(const uint4*)(Blo + bi);
        }
        __syncthreads();

        #pragma unroll
        for (int ks = 0; ks < 2; ks++) {
            // B fragments for 4 n-tiles (hi & lo)
            uint32_t bh[4][2], bl[4][2];
            #pragma unroll
            for (int nt = 0; nt < 4; nt++) {
                uint32_t boff = ((wn * 32 + nt * 8 + b_rowin) * ASTR + ks * 16 + b_colin) * 2;
                ldsm_x2(bh[nt][0], bh[nt][1], aBh + boff);
                ldsm_x2(bl[nt][0], bl[nt][1], aBl + boff);
            }
            #pragma unroll
            for (int mt = 0; mt < 4; mt++) {
                uint32_t aoff = ((wm * 64 + mt * 16 + a_rowin) * ASTR + ks * 16 + a_colin) * 2;
                uint32_t ah0, ah1, ah2, ah3, al0, al1, al2, al3;
                ldsm_x4(ah0, ah1, ah2, ah3, aAh + aoff);
                ldsm_x4(al0, al1, al2, al3, aAl + aoff);
                #pragma unroll
                for (int nt = 0; nt < 4; nt++) {
                    mma16816(acc[mt][nt], ah0, ah1, ah2, ah3, bh[nt][0], bh[nt][1]);
                    mma16816(acc[mt][nt], ah0, ah1, ah2, ah3, bl[nt][0], bl[nt][1]);
                    mma16816(acc[mt][nt], al0, al1, al2, al3, bh[nt][0], bh[nt][1]);
                }
            }
        }
        __syncthreads();
    }

    // ---- epilogue ----
    const int erow = lane >> 2;         // 0..7
    const int ecol = (lane & 3) << 1;   // 0,2,4,6
    #pragma unroll
    for (int mt = 0; mt < 4; mt++) {
        #pragma unroll
        for (int nt = 0; nt < 4; nt++) {
            const int gc = n0 + wn * 32 + nt * 8 + ecol;
            #pragma unroll
            for (int half = 0; half < 2; half++) {
                const int gr = by * BM + wm * 64 + mt * 16 + erow + half * 8;
                if (gr < M) {
                    float v0 = acc[mt][nt][half * 2 + 0];
                    float v1 = acc[mt][nt][half * 2 + 1];
                    if (bias_act) {
                        v0 += bias[gc];     v1 += bias[gc + 1];
                        v0 = (v0 > 0.f) ? v0 : 0.15f * v0;
                        v1 = (v1 > 0.f) ? v1 : 0.15f * v1;
                    }
                    *(float2*)(C + (size_t)gr * N + gc) = make_float2(v0, v1);
                }
            }
        }
    }
}

// ---------------- aggregation: out = [lrelu(] segsum + self [+ bias)] ----------------
template <int F, bool BIAS_ACT>
__global__ void agg_kernel(const float* __restrict__ h, float* __restrict__ out,
                           const float* __restrict__ bias, int n) {
    const int i = blockIdx.x;
    constexpr int VPT = F / 128;
    const int t = threadIdx.x;

    float acc[VPT];
    const float di = g_dis[i];
    const float selfw = di * di;
    const float* hrow = h + (size_t)i * F;
    #pragma unroll
    for (int k = 0; k < VPT; k++) acc[k] = selfw * hrow[t + 128 * k];

    const int beg = g_offsets[i];
    const int end = g_offsets[i + 1];
    for (int j = beg; j < end; j++) {
        const int   s = g_csr_src[j];
        const float w = g_csr_norm[j];
        const float* hs = h + (size_t)s * F;
        #pragma unroll
        for (int k = 0; k < VPT; k++) acc[k] += w * hs[t + 128 * k];
    }
    #pragma unroll
    for (int k = 0; k < VPT; k++) {
        float v = acc[k];
        if (BIAS_ACT) {
            v += bias[t + 128 * k];
            v = (v > 0.f) ? v : 0.15f * v;
        }
        out[(size_t)i * F + t + 128 * k] = v;
    }
}

// ---------------- fused head: h(128) -> 16 -> lrelu(32) -> 2 ----------------
__global__ __launch_bounds__(256)
void head_kernel(const float* __restrict__ h,
                 const float* __restrict__ Wp,  const float* __restrict__ bp,
                 const float* __restrict__ Wf1, const float* __restrict__ bf1,
                 const float* __restrict__ Wf2, const float* __restrict__ bf2,
                 float* __restrict__ out, int n) {
    __shared__ float sWp[128 * 16];
    __shared__ float sWf1[16 * 32];
    __shared__ float sWf2[32 * 2];
    __shared__ float sbp[16], sbf1[32], sbf2[2];

    for (int i = threadIdx.x; i < 128 * 16; i += 256) sWp[i] = Wp[i];
    for (int i = threadIdx.x; i < 16 * 32;  i += 256) sWf1[i] = Wf1[i];
    if (threadIdx.x < 64) sWf2[threadIdx.x] = Wf2[threadIdx.x];
    if (threadIdx.x < 16) sbp[threadIdx.x]  = bp[threadIdx.x];
    if (threadIdx.x < 32) sbf1[threadIdx.x] = bf1[threadIdx.x];
    if (threadIdx.x < 2)  sbf2[threadIdx.x] = bf2[threadIdx.x];
    __syncthreads();

    const int warp = threadIdx.x / 32, lane = threadIdx.x % 32;
    const int node = blockIdx.x * 8 + warp;
    if (node >= n) return;

    float hv[4];
    const float* hr = h + (size_t)node * 128;
    #pragma unroll
    for (int k = 0; k < 4; k++) hv[k] = hr[lane + 32 * k];

    float s16[16];
    #pragma unroll
    for (int j = 0; j < 16; j++) {
        float p = 0.f;
        #pragma unroll
        for (int k = 0; k < 4; k++) p += hv[k] * sWp[(lane + 32 * k) * 16 + j];
        #pragma unroll
        for (int o = 16; o > 0; o >>= 1) p += __shfl_xor_sync(0xffffffffu, p, o);
        s16[j] = p + sbp[j];
    }

    float tv = sbf1[lane];
    #pragma unroll
    for (int k = 0; k < 16; k++) tv += s16[k] * sWf1[k * 32 + lane];
    tv = (tv > 0.f) ? tv : 0.15f * tv;

    float v0 = tv * sWf2[lane * 2 + 0];
    float v1 = tv * sWf2[lane * 2 + 1];
    #pragma unroll
    for (int o = 16; o > 0; o >>= 1) {
        v0 += __shfl_xor_sync(0xffffffffu, v0, o);
        v1 += __shfl_xor_sync(0xffffffffu, v1, o);
    }
    if (lane == 0) {
        out[(size_t)node * 2 + 0] = v0 + sbf2[0];
        out[(size_t)node * 2 + 1] = v1 + sbf2[1];
    }
}

// ---------------- launch ----------------
extern "C" void kernel_launch(void* const* d_in, const int* in_sizes, int n_in,
                              void* d_out, int out_size) {
    const float* x   = (const float*)d_in[0];
    const int*   ei  = (const int*)  d_in[1];
    const float* W1  = (const float*)d_in[3];
    const float* b1  = (const float*)d_in[4];
    const float* W2  = (const float*)d_in[5];
    const float* b2  = (const float*)d_in[6];
    const float* W3  = (const float*)d_in[7];
    const float* b3  = (const float*)d_in[8];
    const float* Wp  = (const float*)d_in[9];
    const float* bp  = (const float*)d_in[10];
    const float* Wf1 = (const float*)d_in[11];
    const float* bf1 = (const float*)d_in[12];
    const float* Wf2 = (const float*)d_in[13];
    const float* bf2 = (const float*)d_in[14];
    float* out = (float*)d_out;

    const int N = in_sizes[0] / 128;
    const int E = in_sizes[1] / 2;
    const int* src = ei;
    const int* dst = ei + E;

    float *h0, *h1;
    __half *ahi, *alo, *bhi, *blo;
    cudaGetSymbolAddress((void**)&h0, g_h0);
    cudaGetSymbolAddress((void**)&h1, g_h1);
    cudaGetSymbolAddress((void**)&ahi, g_Ahi);
    cudaGetSymbolAddress((void**)&alo, g_Alo);
    cudaGetSymbolAddress((void**)&bhi, g_Bhi);
    cudaGetSymbolAddress((void**)&blo, g_Blo);

    const int GM = (N + 127) / 128;   // 157 M-tiles

    // --- preprocessing: degree, norm, CSR-by-dst ---
    zero_indeg_kernel<<<(N + 255) / 256, 256>>>(N);
    count_indeg_kernel<<<(E + 255) / 256, 256>>>(dst, E);
    compute_dis_kernel<<<(N + 255) / 256, 256>>>(N);
    scan_fast_kernel<<<1, 1024>>>(N);
    fill_csr_kernel<<<(E + 255) / 256, 256>>>(src, dst, E);

    // --- layer 1: aggregate-first (F=128), then lrelu(xa @ W1 + b1) ---
    agg_kernel<128, false><<<N, 128>>>(x, h1, nullptr, N);
    {
        int n4 = N * 128 / 4;
        split_fp32_kernel<<<(n4 + 255) / 256, 256>>>(h1, ahi, alo, n4);
        int kn = 128 * 512;
        wsplit_kernel<<<(kn + 255) / 256, 256>>>(W1, bhi, blo, 128, 512);
        dim3 grid(512 / 128, GM);
        gemm_hmma_kernel<<<grid, 256>>>(ahi, alo, bhi, blo, h0, b1, N, 512, 128, 1);
    }
    // --- layer 2: transform-first (512 -> 256), then agg+bias+lrelu ---
    {
        int n4 = N * 512 / 4;
        split_fp32_kernel<<<(n4 + 255) / 256, 256>>>(h0, ahi, alo, n4);
        int kn = 512 * 256;
        wsplit_kernel<<<(kn + 255) / 256, 256>>>(W2, bhi, blo, 512, 256);
        dim3 grid(256 / 128, GM);
        gemm_hmma_kernel<<<grid, 256>>>(ahi, alo, bhi, blo, h1, nullptr, N, 256, 512, 0);
        agg_kernel<256, true><<<N, 128>>>(h1, h0, b2, N);
    }
    // --- layer 3: transform-first (256 -> 128), then agg+bias+lrelu ---
    {
        int n4 = N * 256 / 4;
        split_fp32_kernel<<<(n4 + 255) / 256, 256>>>(h0, ahi, alo, n4);
        int kn = 256 * 128;
        wsplit_kernel<<<(kn + 255) / 256, 256>>>(W3, bhi, blo, 256, 128);
        dim3 grid(128 / 128, GM);
        gemm_hmma_kernel<<<grid, 256>>>(ahi, alo, bhi, blo, h1, nullptr, N, 128, 256, 0);
        agg_kernel<128, true><<<N, 128>>>(h1, h0, b3, N);
    }
    // --- fused head ---
    head_kernel<<<(N + 7) / 8, 256>>>(h0, Wp, bp, Wf1, bf1, Wf2, bf2, out, N);
}

// round 4
// speedup vs baseline: 1.8903x; 1.1201x over previous
#include <cuda_runtime.h>
#include <cuda_fp16.h>
#include <cuda_bf16.h>
#include <cstdint>

// Problem-fixed maxima: N=20000, E=320000, F up to 512
#define MAXN 20000
#define MAXE 320000
#define MAXF 512

// -------- scratch (static device memory; no allocations allowed) --------
__device__ int    g_indeg[MAXN];
__device__ float  g_dis[MAXN];
__device__ int    g_offsets[MAXN + 1];
__device__ int    g_cursor[MAXN];
__device__ int    g_csr_src[MAXE];
__device__ float  g_csr_norm[MAXE];
__device__ float  g_h0[(size_t)MAXN * MAXF];
__device__ float  g_h1[(size_t)MAXN * MAXF];
__device__ __half g_Ahi[(size_t)MAXN * MAXF];
__device__ __half g_Alo[(size_t)MAXN * MAXF];
__device__ __half g_Chi[(size_t)MAXN * MAXF];
__device__ __half g_Clo[(size_t)MAXN * MAXF];
__device__ __half g_Bhi[(size_t)MAXF * MAXF];
__device__ __half g_Blo[(size_t)MAXF * MAXF];

__device__ __forceinline__ uint32_t smem_u32(const void* p) {
    uint32_t a;
    asm("{ .reg .u64 t; cvta.to.shared.u64 t, %1; cvt.u32.u64 %0, t; }" : "=r"(a) : "l"(p));
    return a;
}
__device__ __forceinline__ void ldsm_x4(uint32_t& r0, uint32_t& r1, uint32_t& r2, uint32_t& r3,
                                        uint32_t addr) {
    asm volatile("ldmatrix.sync.aligned.m8n8.x4.shared.b16 {%0,%1,%2,%3}, [%4];"
                 : "=r"(r0), "=r"(r1), "=r"(r2), "=r"(r3) : "r"(addr));
}
__device__ __forceinline__ void ldsm_x2(uint32_t& r0, uint32_t& r1, uint32_t addr) {
    asm volatile("ldmatrix.sync.aligned.m8n8.x2.shared.b16 {%0,%1}, [%2];"
                 : "=r"(r0), "=r"(r1) : "r"(addr));
}
__device__ __forceinline__ void mma16816(float* c, uint32_t a0, uint32_t a1, uint32_t a2,
                                         uint32_t a3, uint32_t b0, uint32_t b1) {
    asm volatile(
        "mma.sync.aligned.m16n8k16.row.col.f32.f16.f16.f32 "
        "{%0,%1,%2,%3}, {%4,%5,%6,%7}, {%8,%9}, {%0,%1,%2,%3};"
        : "+f"(c[0]), "+f"(c[1]), "+f"(c[2]), "+f"(c[3])
        : "r"(a0), "r"(a1), "r"(a2), "r"(a3), "r"(b0), "r"(b1));
}
__device__ __forceinline__ __half2 split_hi2(float a, float b, __half2& lo2) {
    __half ha = __float2half_rn(a), hb = __float2half_rn(b);
    lo2 = __halves2half2(__float2half_rn(a - __half2float(ha)),
                         __float2half_rn(b - __half2float(hb)));
    return __halves2half2(ha, hb);
}

// ---------------- preprocessing ----------------
__global__ void zero_indeg_kernel(int n) {
    int i = blockIdx.x * blockDim.x + threadIdx.x;
    if (i < n) g_indeg[i] = 0;
}
__global__ void count_indeg_kernel(const int* __restrict__ dst, int e) {
    int i = blockIdx.x * blockDim.x + threadIdx.x;
    if (i < e) atomicAdd(&g_indeg[dst[i]], 1);
}
__global__ void compute_dis_kernel(int n) {
    int i = blockIdx.x * blockDim.x + threadIdx.x;
    if (i < n) g_dis[i] = rsqrtf((float)(g_indeg[i] + 1));  // +1 self-loop
}

// spill-free two-pass scan: 1 block, 1024 threads, each owns CH contiguous nodes
__global__ void scan_fast_kernel(int n) {
    const int tid = threadIdx.x;
    const int CH = (n + 1023) >> 10;   // <= 32
    const int base = tid * CH;
    // pass 1: per-thread sum (no local array)
    int s = 0;
    for (int j = 0; j < CH; j++) {
        int i = base + j;
        if (i < n) s += g_indeg[i];
    }
    const int lane = tid & 31, w = tid >> 5;
    int inc = s;
    #pragma unroll
    for (int o = 1; o < 32; o <<= 1) { int t = __shfl_up_sync(~0u, inc, o); if (lane >= o) inc += t; }
    __shared__ int wsum[32];
    if (lane == 31) wsum[w] = inc;
    __syncthreads();
    if (w == 0) {
        int v = wsum[lane];
        int p = v;
        #pragma unroll
        for (int o = 1; o < 32; o <<= 1) { int t = __shfl_up_sync(~0u, p, o); if (lane >= o) p += t; }
        wsum[lane] = p - v;   // exclusive warp offsets
    }
    __syncthreads();
    // pass 2: re-read and emit running prefix
    int run = wsum[w] + (inc - s);
    for (int j = 0; j < CH; j++) {
        int i = base + j;
        if (i < n) {
            int v = g_indeg[i];
            g_offsets[i] = run;
            g_cursor[i]  = run;
            run += v;
        }
    }
    if (tid == 1023) g_offsets[n] = run;
}

__global__ void fill_csr_kernel(const int* __restrict__ src, const int* __restrict__ dst, int e) {
    int i = blockIdx.x * blockDim.x + threadIdx.x;
    if (i < e) {
        int s = src[i], d = dst[i];
        int pos = atomicAdd(&g_cursor[d], 1);
        g_csr_src[pos]  = s;
        g_csr_norm[pos] = g_dis[s] * g_dis[d];
    }
}

// -------- W [K,N] row-major -> Bt [N,K] fp16 hi/lo split --------
__global__ void wsplit_kernel(const float* __restrict__ W, __half* __restrict__ hi,
                              __half* __restrict__ lo, int K, int N) {
    int i = blockIdx.x * blockDim.x + threadIdx.x;
    if (i < K * N) {
        int nn = i / K, kk = i % K;
        float f = W[(size_t)kk * N + nn];
        __half h = __float2half_rn(f);
        hi[i] = h;
        lo[i] = __float2half_rn(f - __half2float(h));
    }
}

// ============ HMMA fp16-split GEMM: C[M,N] = A[M,K] @ Bt[N,K]^T ============
// 128x128 block tile, BK=32, 256 threads (8 warps, 2m x 4n, 64x32 warp tiles).
// EPI=0: plain fp32 out.  EPI=1: bias+lrelu, split fp16 hi/lo out.
#define BM 128
#define BN 128
#define BK 32
#define APAD 8
#define ASTR (BK + APAD)   // 40 halves per row, conflict-free ldmatrix

template <int EPI>
__global__ void __launch_bounds__(256)
gemm_hmma_kernel(const __half* __restrict__ Ahi, const __half* __restrict__ Alo,
                 const __half* __restrict__ Bhi, const __half* __restrict__ Blo,
                 float* __restrict__ Cf, __half* __restrict__ Chi, __half* __restrict__ Clo,
                 const float* __restrict__ bias, int M, int N, int K) {
    __shared__ __half sAh[BM][ASTR];
    __shared__ __half sAl[BM][ASTR];
    __shared__ __half sBh[BN][ASTR];
    __shared__ __half sBl[BN][ASTR];

    const int tid = threadIdx.x;
    const int lane = tid & 31, wid = tid >> 5;
    const int wm = wid & 1;        // 0..1 (m)
    const int wn = wid >> 1;       // 0..3 (n)
    const int by = blockIdx.y;
    const int n0 = blockIdx.x * BN;

    float acc[4][4][4];
    #pragma unroll
    for (int mt = 0; mt < 4; mt++)
        #pragma unroll
        for (int nt = 0; nt < 4; nt++)
            #pragma unroll
            for (int r = 0; r < 4; r++) acc[mt][nt][r] = 0.f;

    const uint32_t aAh = smem_u32(&sAh[0][0]);
    const uint32_t aAl = smem_u32(&sAl[0][0]);
    const uint32_t aBh = smem_u32(&sBh[0][0]);
    const uint32_t aBl = smem_u32(&sBl[0][0]);
    const int a_msel = lane >> 3;              // 0..3
    const int a_rowin = (lane & 7) + ((a_msel & 1) << 3);
    const int a_colin = (a_msel >> 1) << 3;
    const int b_rowin = lane & 7;
    const int b_colin = ((lane >> 3) & 1) << 3;

    const int ldrow = tid >> 2;        // 0..63
    const int ldseg = (tid & 3) << 3;  // 0,8,16,24 halves

    for (int k0 = 0; k0 < K; k0 += BK) {
        #pragma unroll
        for (int h = 0; h < 2; h++) {
            const int row = ldrow + h * 64;
            const int ar = by * BM + row;
            uint4 vh = make_uint4(0, 0, 0, 0), vl = make_uint4(0, 0, 0, 0);
            if (ar < M) {
                size_t ai = (size_t)ar * K + k0 + ldseg;
                vh = *(const uint4*)(Ahi + ai);
                vl = *(const uint4*)(Alo + ai);
            }
            *(uint4*)(&sAh[row][ldseg]) = vh;
            *(uint4*)(&sAl[row][ldseg]) = vl;
            size_t bi = (size_t)(n0 + row) * K + k0 + ldseg;
            *(uint4*)(&sBh[row][ldseg]) = *(const uint4*)(Bhi + bi);
            *(uint4*)(&sBl[row][ldseg]) = *(const uint4*)(Blo + bi);
        }
        __syncthreads();

        #pragma unroll
        for (int ks = 0; ks < 2; ks++) {
            uint32_t bh[4][2], bl[4][2];
            #pragma unroll
            for (int nt = 0; nt < 4; nt++) {
                uint32_t boff = ((wn * 32 + nt * 8 + b_rowin) * ASTR + ks * 16 + b_colin) * 2;
                ldsm_x2(bh[nt][0], bh[nt][1], aBh + boff);
                ldsm_x2(bl[nt][0], bl[nt][1], aBl + boff);
            }
            #pragma unroll
            for (int mt = 0; mt < 4; mt++) {
                uint32_t aoff = ((wm * 64 + mt * 16 + a_rowin) * ASTR + ks * 16 + a_colin) * 2;
                uint32_t ah0, ah1, ah2, ah3, al0, al1, al2, al3;
                ldsm_x4(ah0, ah1, ah2, ah3, aAh + aoff);
                ldsm_x4(al0, al1, al2, al3, aAl + aoff);
                #pragma unroll
                for (int nt = 0; nt < 4; nt++) {
                    mma16816(acc[mt][nt], ah0, ah1, ah2, ah3, bh[nt][0], bh[nt][1]);
                    mma16816(acc[mt][nt], ah0, ah1, ah2, ah3, bl[nt][0], bl[nt][1]);
                    mma16816(acc[mt][nt], al0, al1, al2, al3, bh[nt][0], bh[nt][1]);
                }
            }
        }
        __syncthreads();
    }

    // ---- epilogue ----
    const int erow = lane >> 2;         // 0..7
    const int ecol = (lane & 3) << 1;   // 0,2,4,6
    #pragma unroll
    for (int mt = 0; mt < 4; mt++) {
        #pragma unroll
        for (int nt = 0; nt < 4; nt++) {
            const int gc = n0 + wn * 32 + nt * 8 + ecol;
            #pragma unroll
            for (int half = 0; half < 2; half++) {
                const int gr = by * BM + wm * 64 + mt * 16 + erow + half * 8;
                if (gr < M) {
                    float v0 = acc[mt][nt][half * 2 + 0];
                    float v1 = acc[mt][nt][half * 2 + 1];
                    if (EPI == 1) {
                        v0 += bias[gc];     v1 += bias[gc + 1];
                        v0 = (v0 > 0.f) ? v0 : 0.15f * v0;
                        v1 = (v1 > 0.f) ? v1 : 0.15f * v1;
                        __half2 lo2;
                        __half2 hi2 = split_hi2(v0, v1, lo2);
                        size_t o = (size_t)gr * N + gc;
                        *(__half2*)(Chi + o) = hi2;
                        *(__half2*)(Clo + o) = lo2;
                    } else {
                        *(float2*)(Cf + (size_t)gr * N + gc) = make_float2(v0, v1);
                    }
                }
            }
        }
    }
}

// ------- aggregation (warp per node, float4): out = [lrelu(]sum + self[+bias)] -------
// OUT_SPLIT=1: write fp16 hi/lo split; else fp32.
template <int F, int OUT_SPLIT, int BIASACT>
__global__ void __launch_bounds__(256)
agg_warp_kernel(const float* __restrict__ h, float* __restrict__ outf,
                __half* __restrict__ ohi, __half* __restrict__ olo,
                const float* __restrict__ bias, int n) {
    const int gw = (blockIdx.x * blockDim.x + threadIdx.x) >> 5;
    const int lane = threadIdx.x & 31;
    if (gw >= n) return;
    constexpr int V = F / 128;   // float4 per lane

    float4 acc[V];
    const float di = g_dis[gw];
    const float selfw = di * di;
    const float4* hrow = (const float4*)(h + (size_t)gw * F);
    #pragma unroll
    for (int v = 0; v < V; v++) {
        float4 t = hrow[lane + 32 * v];
        acc[v] = make_float4(selfw * t.x, selfw * t.y, selfw * t.z, selfw * t.w);
    }

    const int beg = g_offsets[gw];
    const int end = g_offsets[gw + 1];
    for (int j = beg; j < end; j++) {
        const int   s = g_csr_src[j];
        const float w = g_csr_norm[j];
        const float4* hs = (const float4*)(h + (size_t)s * F);
        #pragma unroll
        for (int v = 0; v < V; v++) {
            float4 t = hs[lane + 32 * v];
            acc[v].x += w * t.x; acc[v].y += w * t.y;
            acc[v].z += w * t.z; acc[v].w += w * t.w;
        }
    }

    #pragma unroll
    for (int v = 0; v < V; v++) {
        float4 r = acc[v];
        if (BIASACT) {
            const float4 b = ((const float4*)bias)[lane + 32 * v];
            r.x += b.x; r.y += b.y; r.z += b.z; r.w += b.w;
            r.x = (r.x > 0.f) ? r.x : 0.15f * r.x;
            r.y = (r.y > 0.f) ? r.y : 0.15f * r.y;
            r.z = (r.z > 0.f) ? r.z : 0.15f * r.z;
            r.w = (r.w > 0.f) ? r.w : 0.15f * r.w;
        }
        const size_t o = (size_t)gw * F + (lane + 32 * v) * 4;
        if (OUT_SPLIT) {
            __half2 lo0, lo1;
            __half2 hi0 = split_hi2(r.x, r.y, lo0);
            __half2 hi1 = split_hi2(r.z, r.w, lo1);
            *(__half2*)(ohi + o)     = hi0;
            *(__half2*)(ohi + o + 2) = hi1;
            *(__half2*)(olo + o)     = lo0;
            *(__half2*)(olo + o + 2) = lo1;
        } else {
            *(float4*)(outf + o) = r;
        }
    }
}

// ---------------- fused head: h(128) -> 16 -> lrelu(32) -> 2 ----------------
__global__ __launch_bounds__(256)
void head_kernel(const float* __restrict__ h,
                 const float* __restrict__ Wp,  const float* __restrict__ bp,
                 const float* __restrict__ Wf1, const float* __restrict__ bf1,
                 const float* __restrict__ Wf2, const float* __restrict__ bf2,
                 float* __restrict__ out, int n) {
    __shared__ float sWp[128 * 16];
    __shared__ float sWf1[16 * 32];
    __shared__ float sWf2[32 * 2];
    __shared__ float sbp[16], sbf1[32], sbf2[2];

    for (int i = threadIdx.x; i < 128 * 16; i += 256) sWp[i] = Wp[i];
    for (int i = threadIdx.x; i < 16 * 32;  i += 256) sWf1[i] = Wf1[i];
    if (threadIdx.x < 64) sWf2[threadIdx.x] = Wf2[threadIdx.x];
    if (threadIdx.x < 16) sbp[threadIdx.x]  = bp[threadIdx.x];
    if (threadIdx.x < 32) sbf1[threadIdx.x] = bf1[threadIdx.x];
    if (threadIdx.x < 2)  sbf2[threadIdx.x] = bf2[threadIdx.x];
    __syncthreads();

    const int warp = threadIdx.x / 32, lane = threadIdx.x % 32;
    const int node = blockIdx.x * 8 + warp;
    if (node >= n) return;

    float hv[4];
    const float* hr = h + (size_t)node * 128;
    #pragma unroll
    for (int k = 0; k < 4; k++) hv[k] = hr[lane + 32 * k];

    float s16[16];
    #pragma unroll
    for (int j = 0; j < 16; j++) {
        float p = 0.f;
        #pragma unroll
        for (int k = 0; k < 4; k++) p += hv[k] * sWp[(lane + 32 * k) * 16 + j];
        #pragma unroll
        for (int o = 16; o > 0; o >>= 1) p += __shfl_xor_sync(0xffffffffu, p, o);
        s16[j] = p + sbp[j];
    }

    float tv = sbf1[lane];
    #pragma unroll
    for (int k = 0; k < 16; k++) tv += s16[k] * sWf1[k * 32 + lane];
    tv = (tv > 0.f) ? tv : 0.15f * tv;

    float v0 = tv * sWf2[lane * 2 + 0];
    float v1 = tv * sWf2[lane * 2 + 1];
    #pragma unroll
    for (int o = 16; o > 0; o >>= 1) {
        v0 += __shfl_xor_sync(0xffffffffu, v0, o);
        v1 += __shfl_xor_sync(0xffffffffu, v1, o);
    }
    if (lane == 0) {
        out[(size_t)node * 2 + 0] = v0 + sbf2[0];
        out[(size_t)node * 2 + 1] = v1 + sbf2[1];
    }
}

// ---------------- launch ----------------
extern "C" void kernel_launch(void* const* d_in, const int* in_sizes, int n_in,
                              void* d_out, int out_size) {
    const float* x   = (const float*)d_in[0];
    const int*   ei  = (const int*)  d_in[1];
    const float* W1  = (const float*)d_in[3];
    const float* b1  = (const float*)d_in[4];
    const float* W2  = (const float*)d_in[5];
    const float* b2  = (const float*)d_in[6];
    const float* W3  = (const float*)d_in[7];
    const float* b3  = (const float*)d_in[8];
    const float* Wp  = (const float*)d_in[9];
    const float* bp  = (const float*)d_in[10];
    const float* Wf1 = (const float*)d_in[11];
    const float* bf1 = (const float*)d_in[12];
    const float* Wf2 = (const float*)d_in[13];
    const float* bf2 = (const float*)d_in[14];
    float* out = (float*)d_out;

    const int N = in_sizes[0] / 128;
    const int E = in_sizes[1] / 2;
    const int* src = ei;
    const int* dst = ei + E;

    float *h0, *h1;
    __half *ahi, *alo, *chi, *clo, *bhi, *blo;
    cudaGetSymbolAddress((void**)&h0, g_h0);
    cudaGetSymbolAddress((void**)&h1, g_h1);
    cudaGetSymbolAddress((void**)&ahi, g_Ahi);
    cudaGetSymbolAddress((void**)&alo, g_Alo);
    cudaGetSymbolAddress((void**)&chi, g_Chi);
    cudaGetSymbolAddress((void**)&clo, g_Clo);
    cudaGetSymbolAddress((void**)&bhi, g_Bhi);
    cudaGetSymbolAddress((void**)&blo, g_Blo);

    // packed weight-split offsets
    __half *b1hi = bhi,          *b1lo = blo;            // 128*512 = 65536
    __half *b2hi = bhi + 65536,  *b2lo = blo + 65536;    // 512*256 = 131072
    __half *b3hi = bhi + 196608, *b3lo = blo + 196608;   // 256*128 = 32768

    const int GM = (N + 127) / 128;
    const int AGG_BLK = (N * 32 + 255) / 256;   // warp-per-node

    // --- preprocessing + weight splits (weights independent of graph) ---
    zero_indeg_kernel<<<(N + 255) / 256, 256>>>(N);
    wsplit_kernel<<<(128 * 512 + 255) / 256, 256>>>(W1, b1hi, b1lo, 128, 512);
    wsplit_kernel<<<(512 * 256 + 255) / 256, 256>>>(W2, b2hi, b2lo, 512, 256);
    wsplit_kernel<<<(256 * 128 + 255) / 256, 256>>>(W3, b3hi, b3lo, 256, 128);
    count_indeg_kernel<<<(E + 255) / 256, 256>>>(dst, E);
    compute_dis_kernel<<<(N + 255) / 256, 256>>>(N);
    scan_fast_kernel<<<1, 1024>>>(N);
    fill_csr_kernel<<<(E + 255) / 256, 256>>>(src, dst, E);

    // --- layer 1 (aggregate-first): split(agg(x)) -> gemm(+bias+lrelu, split out) ---
    agg_warp_kernel<128, 1, 0><<<AGG_BLK, 256>>>(x, nullptr, ahi, alo, nullptr, N);
    {
        dim3 grid(512 / 128, GM);
        gemm_hmma_kernel<1><<<grid, 256>>>(ahi, alo, b1hi, b1lo, nullptr, chi, clo, b1,
                                           N, 512, 128);
    }
    // --- layer 2 (transform-first): gemm -> agg(+bias+lrelu, split out) ---
    {
        dim3 grid(256 / 128, GM);
        gemm_hmma_kernel<0><<<grid, 256>>>(chi, clo, b2hi, b2lo, h0, nullptr, nullptr,
                                           nullptr, N, 256, 512);
        agg_warp_kernel<256, 1, 1><<<AGG_BLK, 256>>>(h0, nullptr, ahi, alo, b2, N);
    }
    // --- layer 3: gemm -> agg(+bias+lrelu, fp32 out) ---
    {
        dim3 grid(128 / 128, GM);
        gemm_hmma_kernel<0><<<grid, 256>>>(ahi, alo, b3hi, b3lo, h0, nullptr, nullptr,
                                           nullptr, N, 128, 256);
        agg_warp_kernel<128, 0, 1><<<AGG_BLK, 256>>>(h0, h1, nullptr, nullptr, b3, N);
    }
    // --- fused head ---
    head_kernel<<<(N + 7) / 8, 256>>>(h1, Wp, bp, Wf1, bf1, Wf2, bf2, out, N);
}